// round 6
// baseline (speedup 1.0000x reference)
#include <cuda_runtime.h>
#include <cuda_fp16.h>

#define N_NODES 4096
#define N_CHILD 16384
#define DEGREE  64
#define BATCH   128
#define NNZ     (N_NODES * DEGREE)

// Scratch: E_T[c][b] = exp(child_ll[b][c]) in fp16; rows are 256B, 256B-aligned.
__device__ __align__(256) __half g_Eh[(size_t)N_CHILD * BATCH];

// ---------------------------------------------------------------------------
// Kernel 1: exp + transpose + fp16 convert (unchanged from round 5).
// ---------------------------------------------------------------------------
__global__ void __launch_bounds__(256) exp_tr_kernel(
    const float* __restrict__ child_ll) {
    __shared__ float tile[64][65];
    const int c0 = blockIdx.x * 64;
    const int b0 = blockIdx.y * 64;

    const int q  = threadIdx.x & 15;
    const int r0 = threadIdx.x >> 4;
#pragma unroll
    for (int rr = 0; rr < 64; rr += 16) {
        const int r = r0 + rr;
        const float4 v = __ldcg(reinterpret_cast<const float4*>(
            &child_ll[(size_t)(b0 + r) * N_CHILD + c0 + q * 4]));
        tile[q * 4 + 0][r] = v.x;
        tile[q * 4 + 1][r] = v.y;
        tile[q * 4 + 2][r] = v.z;
        tile[q * 4 + 3][r] = v.w;
    }
    __syncthreads();

    const int c = threadIdx.x >> 2;
    const int s = threadIdx.x & 3;
#pragma unroll
    for (int h = 0; h < 2; h++) {
        const int b = s * 8 + h * 32;
        __half2 hv[4];
#pragma unroll
        for (int j = 0; j < 4; j++) {
            const float f0 = __expf(tile[c][b + 2 * j]);
            const float f1 = __expf(tile[c][b + 2 * j + 1]);
            hv[j] = __floats2half2_rn(f0, f1);
        }
        __stcg(reinterpret_cast<uint4*>(&g_Eh[(size_t)(c0 + c) * BATCH + b0 + b]),
               *reinterpret_cast<const uint4*>(hv));
    }
}

// ---------------------------------------------------------------------------
// Kernel 2: gather via cp.async.bulk (UBLKCP -> smem), bypassing L1TEX MSHRs.
// One warp per node; 8 nodes per 256-thread block; grid=512 single wave.
// Per node: 8 chunks x 8 edges; each edge = one 256B bulk copy into a
// double-buffered 2KB stage, completion via mbarrier expect_tx/complete_tx.
// Compute: conflict-free LDS.128 + HFMA2 exactly as before.
// ---------------------------------------------------------------------------
__global__ void __launch_bounds__(256, 4) sum_nodes_kernel(
    const float* __restrict__ log_w, const int* __restrict__ cols,
    float* __restrict__ out) {
    __shared__ __align__(256) unsigned char stage[8][2][2048];
    __shared__ unsigned s_w2[8][64];            // half2(w,w) bit patterns
    __shared__ unsigned s_go[8][64];            // global byte offsets c*256
    __shared__ float    s_o[128][9];            // [batch][node-in-block]
    __shared__ __align__(8) unsigned long long mbar[8][2];

    const int tid   = threadIdx.x;
    const int wid   = tid >> 5;                 // node-in-block 0..7
    const int lane  = tid & 31;
    const int node0 = blockIdx.x * 8;
    const int node  = node0 + wid;
    const int base  = node * DEGREE;

    // Normalized weights (warp shuffle reduction over the 64 edges).
    const float w0 = __expf(log_w[base + lane]);
    const float w1 = __expf(log_w[base + 32 + lane]);
    float ssum = w0 + w1;
#pragma unroll
    for (int o = 16; o; o >>= 1) ssum += __shfl_xor_sync(0xffffffffu, ssum, o);
    const float inv = 1.0f / ssum;
    {
        __half2 a = __float2half2_rn(w0 * inv);
        __half2 b = __float2half2_rn(w1 * inv);
        s_w2[wid][lane]      = *reinterpret_cast<unsigned*>(&a);
        s_w2[wid][lane + 32] = *reinterpret_cast<unsigned*>(&b);
        s_go[wid][lane]      = (unsigned)cols[base + lane] * 256u;
        s_go[wid][lane + 32] = (unsigned)cols[base + 32 + lane] * 256u;
    }

    // mbarrier init (one per warp per buffer), then make visible to TMA proxy.
    if (lane == 0) {
        const unsigned m0 = (unsigned)__cvta_generic_to_shared(&mbar[wid][0]);
        const unsigned m1 = (unsigned)__cvta_generic_to_shared(&mbar[wid][1]);
        asm volatile("mbarrier.init.shared.b64 [%0], 1;" :: "r"(m0) : "memory");
        asm volatile("mbarrier.init.shared.b64 [%0], 1;" :: "r"(m1) : "memory");
        asm volatile("fence.proxy.async.shared::cta;" ::: "memory");
    }
    __syncthreads();

    unsigned long long gbase;
    asm("cvta.to.global.u64 %0, %1;" : "=l"(gbase) : "l"(g_Eh));
    const unsigned stage0 = (unsigned)__cvta_generic_to_shared(&stage[wid][0][0]);
    const unsigned mb0    = (unsigned)__cvta_generic_to_shared(&mbar[wid][0]);

    // Issue chunk k (8 edges) into buffer buf. Lane 0 only: expect_tx then copies.
    auto issue = [&](int k, int buf) {
        if (lane == 0) {
            const unsigned mb = mb0 + buf * 8;
            asm volatile(
                "mbarrier.arrive.expect_tx.shared.b64 _, [%0], %1;"
                :: "r"(mb), "r"(2048u) : "memory");
            const unsigned dstb = stage0 + buf * 2048;
#pragma unroll
            for (int j = 0; j < 8; j++) {
                const unsigned long long src = gbase + s_go[wid][8 * k + j];
                asm volatile(
                    "cp.async.bulk.shared::cluster.global"
                    ".mbarrier::complete_tx::bytes [%0], [%1], %2, [%3];"
                    :: "r"(dstb + j * 256u), "l"(src), "r"(256u), "r"(mb)
                    : "memory");
            }
        }
    };

    issue(0, 0);
    issue(1, 1);

    const int side = lane >> 4;                 // 0: even rows, 1: odd rows
    const int g    = lane & 15;                 // batch-group g*8..g*8+7
    int phase[2] = {0, 0};
    float fa[8] = {0.f, 0.f, 0.f, 0.f, 0.f, 0.f, 0.f, 0.f};

#pragma unroll
    for (int k = 0; k < 8; k++) {
        const int buf = k & 1;
        // Wait for chunk completion.
        {
            const unsigned mb = mb0 + buf * 8;
            asm volatile(
                "{\n\t.reg .pred P;\n\t"
                "WL%=:\n\t"
                "mbarrier.try_wait.parity.acquire.cta.shared::cta.b64 P, [%0], %1, 0x989680;\n\t"
                "@P bra.uni WD%=;\n\t"
                "bra.uni WL%=;\n\t"
                "WD%=:\n\t}"
                :: "r"(mb), "r"((unsigned)phase[buf]) : "memory");
            phase[buf] ^= 1;
        }

        __half2 hacc[4];
#pragma unroll
        for (int t = 0; t < 4; t++) hacc[t] = __float2half2_rn(0.f);

        const unsigned char* sb = &stage[wid][buf][0];
#pragma unroll
        for (int r = 0; r < 4; r++) {
            const int row = 2 * r + side;
            const uint4 p = *reinterpret_cast<const uint4*>(sb + row * 256 + g * 16);
            const unsigned wb = s_w2[wid][8 * k + row];
            const __half2 w2 = *reinterpret_cast<const __half2*>(&wb);
            hacc[0] = __hfma2(w2, *reinterpret_cast<const __half2*>(&p.x), hacc[0]);
            hacc[1] = __hfma2(w2, *reinterpret_cast<const __half2*>(&p.y), hacc[1]);
            hacc[2] = __hfma2(w2, *reinterpret_cast<const __half2*>(&p.z), hacc[2]);
            hacc[3] = __hfma2(w2, *reinterpret_cast<const __half2*>(&p.w), hacc[3]);
        }
#pragma unroll
        for (int t = 0; t < 4; t++) {
            const float2 f = __half22float2(hacc[t]);
            fa[2 * t]     += f.x;
            fa[2 * t + 1] += f.y;
        }

        __syncwarp();                           // all lanes done reading buf
        if (k + 2 < 8) issue(k + 2, buf);
    }

    // Merge even/odd sides; side-0 lanes finish with log.
#pragma unroll
    for (int t = 0; t < 8; t++)
        fa[t] += __shfl_xor_sync(0xffffffffu, fa[t], 16);
    if (side == 0) {
#pragma unroll
        for (int t = 0; t < 8; t++)
            s_o[g * 8 + t][wid] = __logf(fa[t]);
    }
    __syncthreads();

    // Coalesced output: 8 adjacent nodes -> full 32B sectors.
    const int bb = tid >> 1;
    const int h  = (tid & 1) * 4;
    const float4 v = make_float4(s_o[bb][h + 0], s_o[bb][h + 1],
                                 s_o[bb][h + 2], s_o[bb][h + 3]);
    *reinterpret_cast<float4*>(&out[(size_t)bb * N_NODES + node0 + h]) = v;
}

// ---------------------------------------------------------------------------
extern "C" void kernel_launch(void* const* d_in, const int* in_sizes, int n_in,
                              void* d_out, int out_size) {
    const float* child_ll = (const float*)d_in[0];  // [128, 16384] f32
    const float* log_w    = (const float*)d_in[1];  // [262144] f32
    // d_in[2] = rows: structurally repeat(arange(4096), 64) — unused
    const int*   cols     = (const int*)d_in[3];    // [262144] i32
    float*       out      = (float*)d_out;          // [128, 4096] f32

    dim3 tg(N_CHILD / 64, BATCH / 64);              // (256, 2)
    exp_tr_kernel<<<tg, 256>>>(child_ll);
    sum_nodes_kernel<<<N_NODES / 8, 256>>>(log_w, cols, out);
}